// round 1
// baseline (speedup 1.0000x reference)
#include <cuda_runtime.h>

#define N_NODES 100000
#define T_STEPS 12
#define THREADS 256

// shared memory layout (float offsets)
#define OFF_WHH0 0           // 128x32
#define OFF_WIH1 4096        // 128x32
#define OFF_WHH1 8192        // 128x32
#define OFF_A0   12288       // 128  (Wih0 @ W_tp row)
#define OFF_B0   12416       // 128  (Wih0 @ b_tp + bih0 + bhh0)
#define OFF_B1   12544       // 128  (bih1 + bhh1)
#define OFF_WFC1 12672       // 32x16
#define OFF_BFC1 13184       // 16
#define OFF_WFC2 13200       // 16
#define OFF_ST   13216       // state: 5 arrays of [32][256]
#define ST_STRIDE 8192       // 32*256 floats per state array
#define SMEM_FLOATS (OFF_ST + 5 * ST_STRIDE)
#define SMEM_BYTES  (SMEM_FLOATS * 4)   // 216704 bytes

__device__ __forceinline__ float fsig(float x) {
    // sigmoid: graceful at extremes (exp overflow -> inf -> rcp -> 0)
    return __fdividef(1.0f, 1.0f + __expf(-x));
}

__device__ __forceinline__ float ftanhx(float x) {
    x = fminf(fmaxf(x, -30.0f), 30.0f);   // avoid inf/inf NaN
    float e = __expf(-2.0f * x);
    return __fdividef(1.0f - e, 1.0f + e);
}

__global__ void __launch_bounds__(THREADS, 1)
lstm_temporal_kernel(const float* __restrict__ x,
                     const float* __restrict__ Wtp,  const float* __restrict__ btp,
                     const float* __restrict__ Wih0, const float* __restrict__ Whh0,
                     const float* __restrict__ bih0, const float* __restrict__ bhh0,
                     const float* __restrict__ Wih1, const float* __restrict__ Whh1,
                     const float* __restrict__ bih1, const float* __restrict__ bhh1,
                     const float* __restrict__ Wfc1, const float* __restrict__ bfc1,
                     const float* __restrict__ Wfc2, const float* __restrict__ bfc2,
                     float* __restrict__ out)
{
    extern __shared__ float sm[];
    float* sWhh0 = sm + OFF_WHH0;
    float* sWih1 = sm + OFF_WIH1;
    float* sWhh1 = sm + OFF_WHH1;
    float* sa0   = sm + OFF_A0;
    float* sb0   = sm + OFF_B0;
    float* sb1   = sm + OFF_B1;
    float* sWfc1 = sm + OFF_WFC1;
    float* sbfc1 = sm + OFF_BFC1;
    float* sWfc2 = sm + OFF_WFC2;
    float* ST    = sm + OFF_ST;

    const int tid = threadIdx.x;

    // cooperative weight load
    for (int i = tid; i < 4096; i += THREADS) {
        sWhh0[i] = Whh0[i];
        sWih1[i] = Wih1[i];
        sWhh1[i] = Whh1[i];
    }
    for (int i = tid; i < 512; i += THREADS) sWfc1[i] = Wfc1[i];
    if (tid < 16) { sbfc1[tid] = bfc1[tid]; sWfc2[tid] = Wfc2[tid]; }
    // fold rank-1 input projection into per-gate-row constants
    if (tid < 128) {
        float a = 0.0f, b = 0.0f;
        #pragma unroll
        for (int j = 0; j < 16; j++) {
            float w = Wih0[tid * 16 + j];
            a += w * Wtp[j];
            b += w * btp[j];
        }
        sa0[tid] = a;
        sb0[tid] = b + bih0[tid] + bhh0[tid];
        sb1[tid] = bih1[tid] + bhh1[tid];
    }
    __syncthreads();

    const int n = blockIdx.x * THREADS + tid;
    if (n >= N_NODES) return;   // no further __syncthreads below

    // temporal inputs: last 12 features of row n (cols 52..63), 16B-aligned
    float tv[T_STEPS];
    {
        const float4* xp = (const float4*)(x + (size_t)n * 64 + 52);
        float4 v0 = xp[0], v1 = xp[1], v2 = xp[2];
        tv[0] = v0.x; tv[1]  = v0.y; tv[2]  = v0.z; tv[3]  = v0.w;
        tv[4] = v1.x; tv[5]  = v1.y; tv[6]  = v1.z; tv[7]  = v1.w;
        tv[8] = v2.x; tv[9]  = v2.y; tv[10] = v2.z; tv[11] = v2.w;
    }

    // state arrays (per-thread column), rotating roles per step
    float* pH0 = ST;                  // h0
    float* pH1 = ST + ST_STRIDE;      // h1
    float* pHN = ST + 2 * ST_STRIDE;  // scratch / h0_new
    float* pC0 = ST + 3 * ST_STRIDE;
    float* pC1 = ST + 4 * ST_STRIDE;

    #pragma unroll
    for (int j = 0; j < 32; j++) {
        pH0[j * THREADS + tid] = 0.0f;
        pH1[j * THREADS + tid] = 0.0f;
        pC0[j * THREADS + tid] = 0.0f;
        pC1[j * THREADS + tid] = 0.0f;
    }

    for (int s = 0; s < T_STEPS; s++) {
        const float tsc = tv[s];

        // ---- layer 0 ----
        float r0[32];
        #pragma unroll
        for (int j = 0; j < 32; j++) r0[j] = pH0[j * THREADS + tid];

        for (int k = 0; k < 32; k++) {
            const float4* wi = (const float4*)(sWhh0 + (k      ) * 32);
            const float4* wf = (const float4*)(sWhh0 + (k + 32 ) * 32);
            const float4* wg = (const float4*)(sWhh0 + (k + 64 ) * 32);
            const float4* wo = (const float4*)(sWhh0 + (k + 96 ) * 32);
            float ai = 0.f, af = 0.f, ag = 0.f, ao = 0.f;
            #pragma unroll
            for (int q = 0; q < 8; q++) {
                float4 a = wi[q], b = wf[q], c = wg[q], d = wo[q];
                ai += a.x * r0[4*q] + a.y * r0[4*q+1] + a.z * r0[4*q+2] + a.w * r0[4*q+3];
                af += b.x * r0[4*q] + b.y * r0[4*q+1] + b.z * r0[4*q+2] + b.w * r0[4*q+3];
                ag += c.x * r0[4*q] + c.y * r0[4*q+1] + c.z * r0[4*q+2] + c.w * r0[4*q+3];
                ao += d.x * r0[4*q] + d.y * r0[4*q+1] + d.z * r0[4*q+2] + d.w * r0[4*q+3];
            }
            ai += tsc * sa0[k     ] + sb0[k     ];
            af += tsc * sa0[k + 32] + sb0[k + 32];
            ag += tsc * sa0[k + 64] + sb0[k + 64];
            ao += tsc * sa0[k + 96] + sb0[k + 96];

            float cv = pC0[k * THREADS + tid];
            float cn = fsig(af) * cv + fsig(ai) * ftanhx(ag);
            pC0[k * THREADS + tid] = cn;
            pHN[k * THREADS + tid] = fsig(ao) * ftanhx(cn);
        }

        // ---- layer 1 ----  (reads h0_new from pHN, old h1 from pH1; writes h1_new into pH0)
        float rn[32], r1[32];
        #pragma unroll
        for (int j = 0; j < 32; j++) {
            rn[j] = pHN[j * THREADS + tid];
            r1[j] = pH1[j * THREADS + tid];
        }

        for (int k = 0; k < 32; k++) {
            const float4* ii = (const float4*)(sWih1 + (k      ) * 32);
            const float4* fi = (const float4*)(sWih1 + (k + 32 ) * 32);
            const float4* gi = (const float4*)(sWih1 + (k + 64 ) * 32);
            const float4* oi = (const float4*)(sWih1 + (k + 96 ) * 32);
            const float4* ih = (const float4*)(sWhh1 + (k      ) * 32);
            const float4* fh = (const float4*)(sWhh1 + (k + 32 ) * 32);
            const float4* gh = (const float4*)(sWhh1 + (k + 64 ) * 32);
            const float4* oh = (const float4*)(sWhh1 + (k + 96 ) * 32);
            float ai = sb1[k], af = sb1[k + 32], ag = sb1[k + 64], ao = sb1[k + 96];
            #pragma unroll
            for (int q = 0; q < 8; q++) {
                float4 a = ii[q], b = fi[q], c = gi[q], d = oi[q];
                ai += a.x * rn[4*q] + a.y * rn[4*q+1] + a.z * rn[4*q+2] + a.w * rn[4*q+3];
                af += b.x * rn[4*q] + b.y * rn[4*q+1] + b.z * rn[4*q+2] + b.w * rn[4*q+3];
                ag += c.x * rn[4*q] + c.y * rn[4*q+1] + c.z * rn[4*q+2] + c.w * rn[4*q+3];
                ao += d.x * rn[4*q] + d.y * rn[4*q+1] + d.z * rn[4*q+2] + d.w * rn[4*q+3];
            }
            #pragma unroll
            for (int q = 0; q < 8; q++) {
                float4 a = ih[q], b = fh[q], c = gh[q], d = oh[q];
                ai += a.x * r1[4*q] + a.y * r1[4*q+1] + a.z * r1[4*q+2] + a.w * r1[4*q+3];
                af += b.x * r1[4*q] + b.y * r1[4*q+1] + b.z * r1[4*q+2] + b.w * r1[4*q+3];
                ag += c.x * r1[4*q] + c.y * r1[4*q+1] + c.z * r1[4*q+2] + c.w * r1[4*q+3];
                ao += d.x * r1[4*q] + d.y * r1[4*q+1] + d.z * r1[4*q+2] + d.w * r1[4*q+3];
            }

            float cv = pC1[k * THREADS + tid];
            float cn = fsig(af) * cv + fsig(ai) * ftanhx(ag);
            pC1[k * THREADS + tid] = cn;
            pH0[k * THREADS + tid] = fsig(ao) * ftanhx(cn);   // h1_new into dead h0 array
        }

        // rotate roles: h0 <- h0_new(pHN); h1 <- h1_new(pH0); scratch <- pH1
        float* t0 = pHN; float* t1 = pH0; float* ts = pH1;
        pH0 = t0; pH1 = t1; pHN = ts;
    }

    // ---- FC head ----
    float h1f[32];
    #pragma unroll
    for (int j = 0; j < 32; j++) h1f[j] = pH1[j * THREADS + tid];

    float y = bfc2[0];
    #pragma unroll
    for (int m = 0; m < 16; m++) {
        float sacc = sbfc1[m];
        #pragma unroll
        for (int j = 0; j < 32; j++) sacc += h1f[j] * sWfc1[j * 16 + m];
        y += fmaxf(sacc, 0.0f) * sWfc2[m];
    }
    out[n] = y;
}

extern "C" void kernel_launch(void* const* d_in, const int* in_sizes, int n_in,
                              void* d_out, int out_size) {
    const float* x    = (const float*)d_in[0];
    // d_in[1] edge_index, d_in[2..9] GCN weights: dead code in the reference model
    const float* Wtp  = (const float*)d_in[10];
    const float* btp  = (const float*)d_in[11];
    const float* Wih0 = (const float*)d_in[12];
    const float* Whh0 = (const float*)d_in[13];
    const float* bih0 = (const float*)d_in[14];
    const float* bhh0 = (const float*)d_in[15];
    const float* Wih1 = (const float*)d_in[16];
    const float* Whh1 = (const float*)d_in[17];
    const float* bih1 = (const float*)d_in[18];
    const float* bhh1 = (const float*)d_in[19];
    const float* Wfc1 = (const float*)d_in[20];
    const float* bfc1 = (const float*)d_in[21];
    const float* Wfc2 = (const float*)d_in[22];
    const float* bfc2 = (const float*)d_in[23];
    float* out = (float*)d_out;

    cudaFuncSetAttribute(lstm_temporal_kernel,
                         cudaFuncAttributeMaxDynamicSharedMemorySize, SMEM_BYTES);

    int grid = (N_NODES + THREADS - 1) / THREADS;   // 391
    lstm_temporal_kernel<<<grid, THREADS, SMEM_BYTES>>>(
        x, Wtp, btp, Wih0, Whh0, bih0, bhh0,
        Wih1, Whh1, bih1, bhh1, Wfc1, bfc1, Wfc2, bfc2, out);
}

// round 3
// speedup vs baseline: 1.2047x; 1.2047x over previous
#include <cuda_runtime.h>

#define N_NODES 100000
#define T_STEPS 12
#define THREADS 256

// shared memory layout (float offsets)
#define OFF_WHH0 0           // 128x32
#define OFF_WIH1 4096        // 128x32
#define OFF_WHH1 8192        // 128x32
#define OFF_A0   12288       // 128  (Wih0 @ W_tp row)
#define OFF_B0   12416       // 128  (Wih0 @ b_tp + bih0 + bhh0)
#define OFF_B1   12544       // 128  (bih1 + bhh1)
#define OFF_WFC1 12672       // 32x16
#define OFF_BFC1 13184       // 16
#define OFF_WFC2 13200       // 16
#define OFF_H0   13216       // packed u64 [16][256]  (8192 floats)
#define OFF_H1   21408       // packed u64 [16][256]
#define OFF_C0   29600       // float [32][256]
#define OFF_C1   37792       // float [32][256]
#define SMEM_FLOATS 45984
#define SMEM_BYTES  (SMEM_FLOATS * 4)   // 183936 bytes

__device__ __forceinline__ void ffma2(unsigned long long& acc,
                                      unsigned long long a, unsigned long long b) {
    asm("fma.rn.f32x2 %0, %1, %2, %0;" : "+l"(acc) : "l"(a), "l"(b));
}
__device__ __forceinline__ float hsum2(unsigned long long v) {
    float lo, hi;
    asm("mov.b64 {%0, %1}, %2;" : "=f"(lo), "=f"(hi) : "l"(v));
    return lo + hi;
}
__device__ __forceinline__ unsigned long long pack2(float lo, float hi) {
    unsigned long long r;
    asm("mov.b64 %0, {%1, %2};" : "=l"(r) : "f"(lo), "f"(hi));
    return r;
}
__device__ __forceinline__ float tanha(float x) {
    float t;
    asm("tanh.approx.f32 %0, %1;" : "=f"(t) : "f"(x));
    return t;
}
__device__ __forceinline__ float siga(float x) {
    return fmaf(0.5f, tanha(0.5f * x), 0.5f);
}

// 4 gate dot-products for row k over one packed 32-vector; accumulates into gi..go
__device__ __forceinline__ void dot4(const float* __restrict__ W, int k,
                                     const unsigned long long* __restrict__ hp,
                                     float& gi, float& gf, float& gg, float& go) {
    unsigned long long ai = 0, af = 0, ag = 0, ao = 0;
    const ulonglong2* wi = (const ulonglong2*)(W + (k      ) * 32);
    const ulonglong2* wf = (const ulonglong2*)(W + (k + 32 ) * 32);
    const ulonglong2* wg = (const ulonglong2*)(W + (k + 64 ) * 32);
    const ulonglong2* wo = (const ulonglong2*)(W + (k + 96 ) * 32);
    #pragma unroll
    for (int q = 0; q < 8; q++) {
        ulonglong2 a = wi[q], b = wf[q], c = wg[q], d = wo[q];
        unsigned long long h0 = hp[2 * q], h1 = hp[2 * q + 1];
        ffma2(ai, a.x, h0); ffma2(ai, a.y, h1);
        ffma2(af, b.x, h0); ffma2(af, b.y, h1);
        ffma2(ag, c.x, h0); ffma2(ag, c.y, h1);
        ffma2(ao, d.x, h0); ffma2(ao, d.y, h1);
    }
    gi += hsum2(ai); gf += hsum2(af); gg += hsum2(ag); go += hsum2(ao);
}

__global__ void __launch_bounds__(THREADS, 1)
lstm_temporal_kernel(const float* __restrict__ x,
                     const float* __restrict__ Wtp,  const float* __restrict__ btp,
                     const float* __restrict__ Wih0, const float* __restrict__ Whh0,
                     const float* __restrict__ bih0, const float* __restrict__ bhh0,
                     const float* __restrict__ Wih1, const float* __restrict__ Whh1,
                     const float* __restrict__ bih1, const float* __restrict__ bhh1,
                     const float* __restrict__ Wfc1, const float* __restrict__ bfc1,
                     const float* __restrict__ Wfc2, const float* __restrict__ bfc2,
                     float* __restrict__ out)
{
    extern __shared__ float sm[];
    float* sWhh0 = sm + OFF_WHH0;
    float* sWih1 = sm + OFF_WIH1;
    float* sWhh1 = sm + OFF_WHH1;
    float* sa0   = sm + OFF_A0;
    float* sb0   = sm + OFF_B0;
    float* sb1   = sm + OFF_B1;
    float* sWfc1 = sm + OFF_WFC1;
    float* sbfc1 = sm + OFF_BFC1;
    float* sWfc2 = sm + OFF_WFC2;
    unsigned long long* H0 = (unsigned long long*)(sm + OFF_H0);
    unsigned long long* H1 = (unsigned long long*)(sm + OFF_H1);
    float* C0 = sm + OFF_C0;
    float* C1 = sm + OFF_C1;

    const int tid = threadIdx.x;

    // cooperative weight load
    for (int i = tid; i < 4096; i += THREADS) {
        sWhh0[i] = Whh0[i];
        sWih1[i] = Wih1[i];
        sWhh1[i] = Whh1[i];
    }
    for (int i = tid; i < 512; i += THREADS) sWfc1[i] = Wfc1[i];
    if (tid < 16) { sbfc1[tid] = bfc1[tid]; sWfc2[tid] = Wfc2[tid]; }
    // fold rank-1 input projection into per-gate-row constants
    if (tid < 128) {
        float a = 0.0f, b = 0.0f;
        #pragma unroll
        for (int j = 0; j < 16; j++) {
            float w = Wih0[tid * 16 + j];
            a += w * Wtp[j];
            b += w * btp[j];
        }
        sa0[tid] = a;
        sb0[tid] = b + bih0[tid] + bhh0[tid];
        sb1[tid] = bih1[tid] + bhh1[tid];
    }
    __syncthreads();

    const int n = blockIdx.x * THREADS + tid;
    if (n >= N_NODES) return;   // no further __syncthreads below

    // temporal inputs: last 12 features of row n (cols 52..63), 16B-aligned
    float tv[T_STEPS];
    {
        const float4* xp = (const float4*)(x + (size_t)n * 64 + 52);
        float4 v0 = xp[0], v1 = xp[1], v2 = xp[2];
        tv[0] = v0.x; tv[1]  = v0.y; tv[2]  = v0.z; tv[3]  = v0.w;
        tv[4] = v1.x; tv[5]  = v1.y; tv[6]  = v1.z; tv[7]  = v1.w;
        tv[8] = v2.x; tv[9]  = v2.y; tv[10] = v2.z; tv[11] = v2.w;
    }

    // zero state
    #pragma unroll
    for (int j = 0; j < 16; j++) {
        H0[j * THREADS + tid] = 0ULL;
        H1[j * THREADS + tid] = 0ULL;
    }
    #pragma unroll
    for (int k = 0; k < 32; k++) {
        C0[k * THREADS + tid] = 0.0f;
        C1[k * THREADS + tid] = 0.0f;
    }

    #pragma unroll 1
    for (int s = 0; s < T_STEPS; s++) {
        const float tsc = tv[s];

        // ---- layer 0 ----  (old h0 in regs; write new h0 in-place)
        unsigned long long h0p[16];
        #pragma unroll
        for (int j = 0; j < 16; j++) h0p[j] = H0[j * THREADS + tid];

        #pragma unroll 1
        for (int k2 = 0; k2 < 16; k2++) {
            float hn0, hn1;
            {
                const int k = 2 * k2;
                float gi = fmaf(tsc, sa0[k     ], sb0[k     ]);
                float gf = fmaf(tsc, sa0[k + 32], sb0[k + 32]);
                float gg = fmaf(tsc, sa0[k + 64], sb0[k + 64]);
                float go = fmaf(tsc, sa0[k + 96], sb0[k + 96]);
                dot4(sWhh0, k, h0p, gi, gf, gg, go);
                float cv = C0[k * THREADS + tid];
                float cn = siga(gf) * cv + siga(gi) * tanha(gg);
                C0[k * THREADS + tid] = cn;
                hn0 = siga(go) * tanha(cn);
            }
            {
                const int k = 2 * k2 + 1;
                float gi = fmaf(tsc, sa0[k     ], sb0[k     ]);
                float gf = fmaf(tsc, sa0[k + 32], sb0[k + 32]);
                float gg = fmaf(tsc, sa0[k + 64], sb0[k + 64]);
                float go = fmaf(tsc, sa0[k + 96], sb0[k + 96]);
                dot4(sWhh0, k, h0p, gi, gf, gg, go);
                float cv = C0[k * THREADS + tid];
                float cn = siga(gf) * cv + siga(gi) * tanha(gg);
                C0[k * THREADS + tid] = cn;
                hn1 = siga(go) * tanha(cn);
            }
            H0[k2 * THREADS + tid] = pack2(hn0, hn1);
        }

        // ---- layer 1 ----  (hn and old h1 in regs; write new h1 in-place)
        unsigned long long hnp[16], h1p[16];
        #pragma unroll
        for (int j = 0; j < 16; j++) {
            hnp[j] = H0[j * THREADS + tid];
            h1p[j] = H1[j * THREADS + tid];
        }

        #pragma unroll 1
        for (int k2 = 0; k2 < 16; k2++) {
            float hn0, hn1;
            {
                const int k = 2 * k2;
                float gi = sb1[k     ];
                float gf = sb1[k + 32];
                float gg = sb1[k + 64];
                float go = sb1[k + 96];
                dot4(sWih1, k, hnp, gi, gf, gg, go);
                dot4(sWhh1, k, h1p, gi, gf, gg, go);
                float cv = C1[k * THREADS + tid];
                float cn = siga(gf) * cv + siga(gi) * tanha(gg);
                C1[k * THREADS + tid] = cn;
                hn0 = siga(go) * tanha(cn);
            }
            {
                const int k = 2 * k2 + 1;
                float gi = sb1[k     ];
                float gf = sb1[k + 32];
                float gg = sb1[k + 64];
                float go = sb1[k + 96];
                dot4(sWih1, k, hnp, gi, gf, gg, go);
                dot4(sWhh1, k, h1p, gi, gf, gg, go);
                float cv = C1[k * THREADS + tid];
                float cn = siga(gf) * cv + siga(gi) * tanha(gg);
                C1[k * THREADS + tid] = cn;
                hn1 = siga(go) * tanha(cn);
            }
            H1[k2 * THREADS + tid] = pack2(hn0, hn1);
        }
    }

    // ---- FC head ----
    float h1f[32];
    #pragma unroll
    for (int j = 0; j < 16; j++) {
        unsigned long long v = H1[j * THREADS + tid];
        float lo, hi;
        asm("mov.b64 {%0, %1}, %2;" : "=f"(lo), "=f"(hi) : "l"(v));
        h1f[2 * j] = lo; h1f[2 * j + 1] = hi;
    }

    float y = bfc2[0];
    #pragma unroll
    for (int m = 0; m < 16; m++) {
        float sacc = sbfc1[m];
        #pragma unroll
        for (int j = 0; j < 32; j++) sacc += h1f[j] * sWfc1[j * 16 + m];
        y += fmaxf(sacc, 0.0f) * sWfc2[m];
    }
    out[n] = y;
}

extern "C" void kernel_launch(void* const* d_in, const int* in_sizes, int n_in,
                              void* d_out, int out_size) {
    const float* x    = (const float*)d_in[0];
    // d_in[1] edge_index, d_in[2..9] GCN weights: dead code in the reference model
    const float* Wtp  = (const float*)d_in[10];
    const float* btp  = (const float*)d_in[11];
    const float* Wih0 = (const float*)d_in[12];
    const float* Whh0 = (const float*)d_in[13];
    const float* bih0 = (const float*)d_in[14];
    const float* bhh0 = (const float*)d_in[15];
    const float* Wih1 = (const float*)d_in[16];
    const float* Whh1 = (const float*)d_in[17];
    const float* bih1 = (const float*)d_in[18];
    const float* bhh1 = (const float*)d_in[19];
    const float* Wfc1 = (const float*)d_in[20];
    const float* bfc1 = (const float*)d_in[21];
    const float* Wfc2 = (const float*)d_in[22];
    const float* bfc2 = (const float*)d_in[23];
    float* out = (float*)d_out;

    cudaFuncSetAttribute(lstm_temporal_kernel,
                         cudaFuncAttributeMaxDynamicSharedMemorySize, SMEM_BYTES);

    int grid = (N_NODES + THREADS - 1) / THREADS;   // 391
    lstm_temporal_kernel<<<grid, THREADS, SMEM_BYTES>>>(
        x, Wtp, btp, Wih0, Whh0, bih0, bhh0,
        Wih1, Whh1, bih1, bhh1, Wfc1, bfc1, Wfc2, bfc2, out);
}

// round 4
// speedup vs baseline: 1.2121x; 1.0062x over previous
#include <cuda_runtime.h>

#define N_NODES 100000
#define T_STEPS 12
#define THREADS 256
#define NODES_PER_CTA 128

// shared memory layout (float offsets)
#define OFF_WHH0 0           // 128x32
#define OFF_WIH1 4096        // 128x32
#define OFF_WHH1 8192        // 128x32
#define OFF_A0   12288       // 128  (Wih0 @ W_tp row)
#define OFF_B0   12416       // 128  (Wih0 @ b_tp + bih0 + bhh0)
#define OFF_B1   12544       // 128  (bih1 + bhh1)
#define OFF_FCB  12672       // sbfc1[16] + sWfc2[16]
#define OFF_H0   12704       // u64[16][128]  (4096 floats)
#define OFF_H1   16800       // u64[16][128]
#define OFF_C1   20896       // float[16][256]; reused for Wfc1[512] in the tail
#define SMEM_FLOATS 24992
#define SMEM_BYTES  (SMEM_FLOATS * 4)   // 99968 bytes -> 2 CTAs/SM

__device__ __forceinline__ void ffma2(unsigned long long& acc,
                                      unsigned long long a, unsigned long long b) {
    asm("fma.rn.f32x2 %0, %1, %2, %0;" : "+l"(acc) : "l"(a), "l"(b));
}
__device__ __forceinline__ float hsum2(unsigned long long v) {
    float lo, hi;
    asm("mov.b64 {%0, %1}, %2;" : "=f"(lo), "=f"(hi) : "l"(v));
    return lo + hi;
}
__device__ __forceinline__ unsigned long long pack2(float lo, float hi) {
    unsigned long long r;
    asm("mov.b64 %0, {%1, %2};" : "=l"(r) : "f"(lo), "f"(hi));
    return r;
}
__device__ __forceinline__ float tanha(float x) {
    float t;
    asm("tanh.approx.f32 %0, %1;" : "=f"(t) : "f"(x));
    return t;
}
__device__ __forceinline__ float siga(float x) {
    return fmaf(0.5f, tanha(0.5f * x), 0.5f);
}

// 4 gate dot-products for row k over a packed 32-vector; accumulates into gi..go
__device__ __forceinline__ void dot4(const float* __restrict__ W, int k,
                                     const unsigned long long* __restrict__ hp,
                                     float& gi, float& gf, float& gg, float& go) {
    unsigned long long ai = 0, af = 0, ag = 0, ao = 0;
    const ulonglong2* wi = (const ulonglong2*)(W + (k      ) * 32);
    const ulonglong2* wf = (const ulonglong2*)(W + (k + 32 ) * 32);
    const ulonglong2* wg = (const ulonglong2*)(W + (k + 64 ) * 32);
    const ulonglong2* wo = (const ulonglong2*)(W + (k + 96 ) * 32);
    #pragma unroll
    for (int q = 0; q < 8; q++) {
        ulonglong2 a = wi[q], b = wf[q], c = wg[q], d = wo[q];
        unsigned long long h0 = hp[2 * q], h1 = hp[2 * q + 1];
        ffma2(ai, a.x, h0); ffma2(ai, a.y, h1);
        ffma2(af, b.x, h0); ffma2(af, b.y, h1);
        ffma2(ag, c.x, h0); ffma2(ag, c.y, h1);
        ffma2(ao, d.x, h0); ffma2(ao, d.y, h1);
    }
    gi += hsum2(ai); gf += hsum2(af); gg += hsum2(ag); go += hsum2(ao);
}

__global__ void __launch_bounds__(THREADS, 2)
lstm_temporal_kernel(const float* __restrict__ x,
                     const float* __restrict__ Wtp,  const float* __restrict__ btp,
                     const float* __restrict__ Wih0, const float* __restrict__ Whh0,
                     const float* __restrict__ bih0, const float* __restrict__ bhh0,
                     const float* __restrict__ Wih1, const float* __restrict__ Whh1,
                     const float* __restrict__ bih1, const float* __restrict__ bhh1,
                     const float* __restrict__ Wfc1, const float* __restrict__ bfc1,
                     const float* __restrict__ Wfc2, const float* __restrict__ bfc2,
                     float* __restrict__ out)
{
    extern __shared__ float sm[];
    float* sWhh0 = sm + OFF_WHH0;
    float* sWih1 = sm + OFF_WIH1;
    float* sWhh1 = sm + OFF_WHH1;
    float* sa0   = sm + OFF_A0;
    float* sb0   = sm + OFF_B0;
    float* sb1   = sm + OFF_B1;
    float* sbfc1 = sm + OFF_FCB;        // 16
    float* sWfc2 = sm + OFF_FCB + 16;   // 16
    unsigned long long* H0u = (unsigned long long*)(sm + OFF_H0);
    unsigned long long* H1u = (unsigned long long*)(sm + OFF_H1);
    float* C1h = sm + OFF_C1;

    const int tid  = threadIdx.x;
    const int node = tid & (NODES_PER_CTA - 1);
    const int half = tid >> 7;          // 0 or 1 (warp-uniform)
    const int kb   = half << 4;         // row base: 0 or 16

    // cooperative weight load (vectorized)
    {
        const float4* A = (const float4*)Whh0;
        const float4* B = (const float4*)Wih1;
        const float4* C = (const float4*)Whh1;
        float4* a = (float4*)sWhh0;
        float4* b = (float4*)sWih1;
        float4* c = (float4*)sWhh1;
        #pragma unroll
        for (int i = tid; i < 1024; i += THREADS) {
            a[i] = A[i]; b[i] = B[i]; c[i] = C[i];
        }
    }
    if (tid < 16) { sbfc1[tid] = bfc1[tid]; sWfc2[tid] = Wfc2[tid]; }
    // fold rank-1 input projection into per-gate-row constants
    if (tid < 128) {
        float a = 0.0f, b = 0.0f;
        #pragma unroll
        for (int j = 0; j < 16; j++) {
            float w = Wih0[tid * 16 + j];
            a += w * Wtp[j];
            b += w * btp[j];
        }
        sa0[tid] = a;
        sb0[tid] = b + bih0[tid] + bhh0[tid];
        sb1[tid] = bih1[tid] + bhh1[tid];
    }
    // zero h state + c1 state
    for (int i = tid; i < 2048; i += THREADS) { H0u[i] = 0ULL; H1u[i] = 0ULL; }
    #pragma unroll
    for (int r = 0; r < 16; r++) C1h[r * THREADS + tid] = 0.0f;
    __syncthreads();

    const int ng = blockIdx.x * NODES_PER_CTA + node;             // global node
    const int nc = (ng < N_NODES) ? ng : (N_NODES - 1);           // clamped for loads
    const float* xr = x + (size_t)nc * 64 + 52;

    float c0r[16];
    #pragma unroll
    for (int r = 0; r < 16; r++) c0r[r] = 0.0f;

    #pragma unroll 1
    for (int s = 0; s < T_STEPS; s++) {
        const float tsc = __ldg(xr + s);

        // ---- layer 0 ----
        unsigned long long hp[16];
        #pragma unroll
        for (int j = 0; j < 16; j++) hp[j] = H0u[j * NODES_PER_CTA + node];
        __syncthreads();   // (a) all h0 reads done before overwrites

        #pragma unroll
        for (int p = 0; p < 8; p++) {
            float hn0, hn1;
            {
                const int k = kb + 2 * p;
                float gi = fmaf(tsc, sa0[k     ], sb0[k     ]);
                float gf = fmaf(tsc, sa0[k + 32], sb0[k + 32]);
                float gg = fmaf(tsc, sa0[k + 64], sb0[k + 64]);
                float go = fmaf(tsc, sa0[k + 96], sb0[k + 96]);
                dot4(sWhh0, k, hp, gi, gf, gg, go);
                float cn = siga(gf) * c0r[2 * p] + siga(gi) * tanha(gg);
                c0r[2 * p] = cn;
                hn0 = siga(go) * tanha(cn);
            }
            {
                const int k = kb + 2 * p + 1;
                float gi = fmaf(tsc, sa0[k     ], sb0[k     ]);
                float gf = fmaf(tsc, sa0[k + 32], sb0[k + 32]);
                float gg = fmaf(tsc, sa0[k + 64], sb0[k + 64]);
                float go = fmaf(tsc, sa0[k + 96], sb0[k + 96]);
                dot4(sWhh0, k, hp, gi, gf, gg, go);
                float cn = siga(gf) * c0r[2 * p + 1] + siga(gi) * tanha(gg);
                c0r[2 * p + 1] = cn;
                hn1 = siga(go) * tanha(cn);
            }
            H0u[(half * 8 + p) * NODES_PER_CTA + node] = pack2(hn0, hn1);
        }
        __syncthreads();   // (b) new h0 complete before layer-1 reads

        // ---- layer 1 ----
        unsigned long long hnp[16], h1p[16];
        #pragma unroll
        for (int j = 0; j < 16; j++) {
            hnp[j] = H0u[j * NODES_PER_CTA + node];
            h1p[j] = H1u[j * NODES_PER_CTA + node];
        }
        __syncthreads();   // (c) all h1 reads done before overwrites

        #pragma unroll 1
        for (int p = 0; p < 8; p++) {
            float hn0, hn1;
            {
                const int k = kb + 2 * p;
                float gi = sb1[k     ];
                float gf = sb1[k + 32];
                float gg = sb1[k + 64];
                float go = sb1[k + 96];
                dot4(sWih1, k, hnp, gi, gf, gg, go);
                dot4(sWhh1, k, h1p, gi, gf, gg, go);
                float cv = C1h[(2 * p) * THREADS + tid];
                float cn = siga(gf) * cv + siga(gi) * tanha(gg);
                C1h[(2 * p) * THREADS + tid] = cn;
                hn0 = siga(go) * tanha(cn);
            }
            {
                const int k = kb + 2 * p + 1;
                float gi = sb1[k     ];
                float gf = sb1[k + 32];
                float gg = sb1[k + 64];
                float go = sb1[k + 96];
                dot4(sWih1, k, hnp, gi, gf, gg, go);
                dot4(sWhh1, k, h1p, gi, gf, gg, go);
                float cv = C1h[(2 * p + 1) * THREADS + tid];
                float cn = siga(gf) * cv + siga(gi) * tanha(gg);
                C1h[(2 * p + 1) * THREADS + tid] = cn;
                hn1 = siga(go) * tanha(cn);
            }
            H1u[(half * 8 + p) * NODES_PER_CTA + node] = pack2(hn0, hn1);
        }
        __syncthreads();   // (d) new h1 complete before next step
    }

    // ---- FC head ----  (reuse dead C1 smem for Wfc1)
    float* sWfc1 = C1h;
    for (int i = tid; i < 512; i += THREADS) sWfc1[i] = Wfc1[i];
    __syncthreads();

    if (half == 0 && ng < N_NODES) {
        float h1f[32];
        #pragma unroll
        for (int j = 0; j < 16; j++) {
            unsigned long long v = H1u[j * NODES_PER_CTA + node];
            float lo, hi;
            asm("mov.b64 {%0, %1}, %2;" : "=f"(lo), "=f"(hi) : "l"(v));
            h1f[2 * j] = lo; h1f[2 * j + 1] = hi;
        }
        float y = __ldg(bfc2);
        #pragma unroll
        for (int m = 0; m < 16; m++) {
            float sacc = sbfc1[m];
            #pragma unroll
            for (int j = 0; j < 32; j++) sacc += h1f[j] * sWfc1[j * 16 + m];
            y += fmaxf(sacc, 0.0f) * sWfc2[m];
        }
        out[ng] = y;
    }
}

extern "C" void kernel_launch(void* const* d_in, const int* in_sizes, int n_in,
                              void* d_out, int out_size) {
    const float* x    = (const float*)d_in[0];
    // d_in[1] edge_index, d_in[2..9] GCN weights: dead code in the reference model
    const float* Wtp  = (const float*)d_in[10];
    const float* btp  = (const float*)d_in[11];
    const float* Wih0 = (const float*)d_in[12];
    const float* Whh0 = (const float*)d_in[13];
    const float* bih0 = (const float*)d_in[14];
    const float* bhh0 = (const float*)d_in[15];
    const float* Wih1 = (const float*)d_in[16];
    const float* Whh1 = (const float*)d_in[17];
    const float* bih1 = (const float*)d_in[18];
    const float* bhh1 = (const float*)d_in[19];
    const float* Wfc1 = (const float*)d_in[20];
    const float* bfc1 = (const float*)d_in[21];
    const float* Wfc2 = (const float*)d_in[22];
    const float* bfc2 = (const float*)d_in[23];
    float* out = (float*)d_out;

    cudaFuncSetAttribute(lstm_temporal_kernel,
                         cudaFuncAttributeMaxDynamicSharedMemorySize, SMEM_BYTES);

    int grid = (N_NODES + NODES_PER_CTA - 1) / NODES_PER_CTA;   // 782
    lstm_temporal_kernel<<<grid, THREADS, SMEM_BYTES>>>(
        x, Wtp, btp, Wih0, Whh0, bih0, bhh0,
        Wih1, Whh1, bih1, bhh1, Wfc1, bfc1, Wfc2, bfc2, out);
}

// round 11
// speedup vs baseline: 4.4579x; 3.6777x over previous
#include <cuda_runtime.h>
#include <cuda_bf16.h>
#include <cstdint>

#define N_NODES 100000
#define T_STEPS 12
#define THREADS 128

// ---------- smem byte offsets ----------
#define SM_W0H 0          // 128 rows x 80B   (Whh0 hi, K=32)
#define SM_W0L 10240      // 128 rows x 80B   (Whh0 lo)
#define SM_W1H 20480      // 128 rows x 144B  ([Wih1|Whh1] hi, K=64)
#define SM_W1L 38912      // 128 rows x 144B  (lo)
#define SM_HBH 57344      // 128 nodes x 144B (h = [h0|h1] hi, K=64)
#define SM_HBL 75776      // 128 nodes x 144B (h lo)
#define SM_TSC 94208      // [12][128] f32
#define SM_SA0 100352     // 128 f
#define SM_SB0 100864     // 128 f
#define SM_SB1 101376     // 128 f
#define SM_FC1 101888     // 512 f
#define SM_FCB 103936     // bfc1[16] @ +0, wfc2[16] @ +64
#define SMEM_BYTES 104192 // -> 2 CTAs/SM

// ---------- helpers ----------
__device__ __forceinline__ float tanha(float x) {
    float t; asm("tanh.approx.f32 %0, %1;" : "=f"(t) : "f"(x)); return t;
}
__device__ __forceinline__ float siga(float x) { return fmaf(0.5f, tanha(0.5f * x), 0.5f); }

__device__ __forceinline__ uint32_t pk2(float a, float b) {
    __nv_bfloat162 t = __floats2bfloat162_rn(a, b);
    return *(uint32_t*)&t;
}
__device__ __forceinline__ void put_split(char* bh, char* bl, int off, float w) {
    __nv_bfloat16 h = __float2bfloat16(w);
    float r = w - __bfloat162float(h);
    __nv_bfloat16 l = __float2bfloat16(r);
    *(uint16_t*)(bh + off) = *(uint16_t*)&h;
    *(uint16_t*)(bl + off) = *(uint16_t*)&l;
}
// D += A(m16k16, row) x B(k16n8, col), bf16 -> f32
__device__ __forceinline__ void mma16816(float* d, const uint32_t* a, const uint32_t* b) {
    asm volatile("mma.sync.aligned.m16n8k16.row.col.f32.bf16.bf16.f32 "
                 "{%0,%1,%2,%3}, {%4,%5,%6,%7}, {%8,%9}, {%0,%1,%2,%3};"
                 : "+f"(d[0]), "+f"(d[1]), "+f"(d[2]), "+f"(d[3])
                 : "r"(a[0]), "r"(a[1]), "r"(a[2]), "r"(a[3]), "r"(b[0]), "r"(b[1]));
}

__global__ void __launch_bounds__(THREADS)
lstm_hmma_kernel(const float* __restrict__ x,
                 const float* __restrict__ Wtp,  const float* __restrict__ btp,
                 const float* __restrict__ Wih0, const float* __restrict__ Whh0,
                 const float* __restrict__ bih0, const float* __restrict__ bhh0,
                 const float* __restrict__ Wih1, const float* __restrict__ Whh1,
                 const float* __restrict__ bih1, const float* __restrict__ bhh1,
                 const float* __restrict__ Wfc1, const float* __restrict__ bfc1,
                 const float* __restrict__ Wfc2, const float* __restrict__ bfc2,
                 float* __restrict__ out)
{
    extern __shared__ char smc[];
    float* sa0   = (float*)(smc + SM_SA0);
    float* sb0   = (float*)(smc + SM_SB0);
    float* sb1   = (float*)(smc + SM_SB1);
    float* sWfc1 = (float*)(smc + SM_FC1);
    float* sbfc1 = (float*)(smc + SM_FCB);
    float* sWfc2 = (float*)(smc + SM_FCB + 64);
    float* stsc  = (float*)(smc + SM_TSC);

    const int tid  = threadIdx.x;
    const int lane = tid & 31;
    const int warp = tid >> 5;
    const int gid  = lane >> 2;   // fragment group id (0..7)
    const int tig  = lane & 3;    // thread-in-group (0..3)
    const int NB   = warp * 32;   // this warp's node base (within CTA)

    // ---- weights -> bf16 hi/lo smem tiles ----
    for (int i = tid; i < 4096; i += THREADS) {
        int j = i >> 5, k = i & 31;
        put_split(smc + SM_W0H, smc + SM_W0L, j * 80 + k * 2,        Whh0[i]);
        put_split(smc + SM_W1H, smc + SM_W1L, j * 144 + k * 2,      Wih1[i]);
        put_split(smc + SM_W1H, smc + SM_W1L, j * 144 + 64 + k * 2, Whh1[i]);
    }
    // folded rank-1 input projection + biases  (tid == gate row, 0..127)
    {
        float a = 0.f, b = 0.f;
        #pragma unroll
        for (int j = 0; j < 16; j++) { float w = Wih0[tid * 16 + j]; a += w * Wtp[j]; b += w * btp[j]; }
        sa0[tid] = a;
        sb0[tid] = b + bih0[tid] + bhh0[tid];
        sb1[tid] = bih1[tid] + bhh1[tid];
    }
    for (int i = tid; i < 512; i += THREADS) sWfc1[i] = Wfc1[i];
    if (tid < 16) { sbfc1[tid] = bfc1[tid]; sWfc2[tid] = Wfc2[tid]; }

    // ---- temporal inputs to smem [s][node] ----
    const int ng = blockIdx.x * THREADS + tid;
    const int nc = (ng < N_NODES) ? ng : (N_NODES - 1);
    {
        const float4* xp = (const float4*)(x + (size_t)nc * 64 + 52);
        float4 v0 = xp[0], v1 = xp[1], v2 = xp[2];
        float tv[12] = {v0.x,v0.y,v0.z,v0.w, v1.x,v1.y,v1.z,v1.w, v2.x,v2.y,v2.z,v2.w};
        #pragma unroll
        for (int s = 0; s < 12; s++) stsc[s * 128 + tid] = tv[s];
    }
    // ---- zero h buffers (h0 = h1 = 0) ----
    {
        uint4 z = {0, 0, 0, 0};
        uint4* p = (uint4*)(smc + SM_HBH);
        for (int i = tid; i < 2304; i += THREADS) p[i] = z;   // 36864 B
    }
    __syncthreads();

    // c-states in registers; index = (m*4 + njb)*2 + e  (m: node slot 0..3)
    float c0[32], c1[32];
    #pragma unroll
    for (int i = 0; i < 32; i++) { c0[i] = 0.f; c1[i] = 0.f; }

    #pragma unroll 1
    for (int s = 0; s < T_STEPS; s++) {
        float tscm[4];
        #pragma unroll
        for (int m = 0; m < 4; m++)
            tscm[m] = stsc[s * 128 + NB + (m >> 1) * 16 + ((m & 1) << 3) + gid];

        // ================= layer 0 : G = h0 @ Whh0^T  (K=32) =================
        uint32_t A0h[2][2][4], A0l[2][2][4];
        #pragma unroll
        for (int mt = 0; mt < 2; mt++)
            #pragma unroll
            for (int kt = 0; kt < 2; kt++) {
                int o = (NB + mt * 16 + gid) * 144 + kt * 32 + tig * 4;
                A0h[mt][kt][0] = *(uint32_t*)(smc + SM_HBH + o);
                A0h[mt][kt][1] = *(uint32_t*)(smc + SM_HBH + o + 8 * 144);
                A0h[mt][kt][2] = *(uint32_t*)(smc + SM_HBH + o + 16);
                A0h[mt][kt][3] = *(uint32_t*)(smc + SM_HBH + o + 8 * 144 + 16);
                A0l[mt][kt][0] = *(uint32_t*)(smc + SM_HBL + o);
                A0l[mt][kt][1] = *(uint32_t*)(smc + SM_HBL + o + 8 * 144);
                A0l[mt][kt][2] = *(uint32_t*)(smc + SM_HBL + o + 16);
                A0l[mt][kt][3] = *(uint32_t*)(smc + SM_HBL + o + 8 * 144 + 16);
            }

        #pragma unroll
        for (int njb = 0; njb < 4; njb++) {
            float D[2][4][4];
            #pragma unroll
            for (int g = 0; g < 4; g++)
                #pragma unroll
                for (int e = 0; e < 2; e++) {
                    int n = njb * 8 + g * 32 + tig * 2 + e;
                    float sa = sa0[n], sv = sb0[n];
                    #pragma unroll
                    for (int m = 0; m < 4; m++)
                        D[m >> 1][g][(m & 1) * 2 + e] = fmaf(tscm[m], sa, sv);
                }
            #pragma unroll
            for (int g = 0; g < 4; g++) {
                int nb = (njb + g * 4) * 8;
                #pragma unroll
                for (int kt = 0; kt < 2; kt++) {
                    int o = (nb + gid) * 80 + kt * 32 + tig * 4;
                    uint32_t bh[2] = { *(uint32_t*)(smc + SM_W0H + o), *(uint32_t*)(smc + SM_W0H + o + 16) };
                    uint32_t bl[2] = { *(uint32_t*)(smc + SM_W0L + o), *(uint32_t*)(smc + SM_W0L + o + 16) };
                    #pragma unroll
                    for (int mt = 0; mt < 2; mt++) {
                        mma16816(D[mt][g], A0h[mt][kt], bh);
                        mma16816(D[mt][g], A0h[mt][kt], bl);
                        mma16816(D[mt][g], A0l[mt][kt], bh);
                    }
                }
            }
            // epilogue: activations, c0 update, h0_new -> hbuf cols 0..31
            #pragma unroll
            for (int m = 0; m < 4; m++) {
                int mt = m >> 1, rh = m & 1;
                float hv[2], hlo[2];
                #pragma unroll
                for (int e = 0; e < 2; e++) {
                    int idx = rh * 2 + e, ci = (m * 4 + njb) * 2 + e;
                    float cn = siga(D[mt][1][idx]) * c0[ci]
                             + siga(D[mt][0][idx]) * tanha(D[mt][2][idx]);
                    c0[ci] = cn;
                    float h = siga(D[mt][3][idx]) * tanha(cn);
                    hv[e] = h;
                    hlo[e] = h - __bfloat162float(__float2bfloat16(h));
                }
                int o = (NB + mt * 16 + rh * 8 + gid) * 144 + njb * 16 + tig * 4;
                *(uint32_t*)(smc + SM_HBH + o) = pk2(hv[0], hv[1]);
                *(uint32_t*)(smc + SM_HBL + o) = pk2(hlo[0], hlo[1]);
            }
        }
        __syncwarp();

        // ============ layer 1 : G = [h0new|h1] @ [Wih1|Whh1]^T  (K=64) ============
        uint32_t A1h[2][4][4], A1l[2][4][4];
        #pragma unroll
        for (int mt = 0; mt < 2; mt++)
            #pragma unroll
            for (int kt = 0; kt < 4; kt++) {
                int o = (NB + mt * 16 + gid) * 144 + kt * 32 + tig * 4;
                A1h[mt][kt][0] = *(uint32_t*)(smc + SM_HBH + o);
                A1h[mt][kt][1] = *(uint32_t*)(smc + SM_HBH + o + 8 * 144);
                A1h[mt][kt][2] = *(uint32_t*)(smc + SM_HBH + o + 16);
                A1h[mt][kt][3] = *(uint32_t*)(smc + SM_HBH + o + 8 * 144 + 16);
                A1l[mt][kt][0] = *(uint32_t*)(smc + SM_HBL + o);
                A1l[mt][kt][1] = *(uint32_t*)(smc + SM_HBL + o + 8 * 144);
                A1l[mt][kt][2] = *(uint32_t*)(smc + SM_HBL + o + 16);
                A1l[mt][kt][3] = *(uint32_t*)(smc + SM_HBL + o + 8 * 144 + 16);
            }

        #pragma unroll
        for (int njb = 0; njb < 4; njb++) {
            float D[2][4][4];
            #pragma unroll
            for (int g = 0; g < 4; g++)
                #pragma unroll
                for (int e = 0; e < 2; e++) {
                    float sv = sb1[njb * 8 + g * 32 + tig * 2 + e];
                    #pragma unroll
                    for (int m = 0; m < 4; m++)
                        D[m >> 1][g][(m & 1) * 2 + e] = sv;
                }
            #pragma unroll
            for (int g = 0; g < 4; g++) {
                int nb = (njb + g * 4) * 8;
                #pragma unroll
                for (int kt = 0; kt < 4; kt++) {
                    int o = (nb + gid) * 144 + kt * 32 + tig * 4;
                    uint32_t bh[2] = { *(uint32_t*)(smc + SM_W1H + o), *(uint32_t*)(smc + SM_W1H + o + 16) };
                    uint32_t bl[2] = { *(uint32_t*)(smc + SM_W1L + o), *(uint32_t*)(smc + SM_W1L + o + 16) };
                    #pragma unroll
                    for (int mt = 0; mt < 2; mt++) {
                        mma16816(D[mt][g], A1h[mt][kt], bh);
                        mma16816(D[mt][g], A1h[mt][kt], bl);
                        mma16816(D[mt][g], A1l[mt][kt], bh);
                    }
                }
            }
            // epilogue: activations, c1 update, h1_new -> hbuf cols 32..63
            #pragma unroll
            for (int m = 0; m < 4; m++) {
                int mt = m >> 1, rh = m & 1;
                float hv[2], hlo[2];
                #pragma unroll
                for (int e = 0; e < 2; e++) {
                    int idx = rh * 2 + e, ci = (m * 4 + njb) * 2 + e;
                    float cn = siga(D[mt][1][idx]) * c1[ci]
                             + siga(D[mt][0][idx]) * tanha(D[mt][2][idx]);
                    c1[ci] = cn;
                    float h = siga(D[mt][3][idx]) * tanha(cn);
                    hv[e] = h;
                    hlo[e] = h - __bfloat162float(__float2bfloat16(h));
                }
                int o = (NB + mt * 16 + rh * 8 + gid) * 144 + 64 + njb * 16 + tig * 4;
                *(uint32_t*)(smc + SM_HBH + o) = pk2(hv[0], hv[1]);
                *(uint32_t*)(smc + SM_HBL + o) = pk2(hlo[0], hlo[1]);
            }
        }
        __syncwarp();
    }

    // ---- FC head: thread tid = node tid (same warp wrote its h) ----
    float h1f[32];
    #pragma unroll
    for (int j2 = 0; j2 < 16; j2++) {
        uint32_t vh = *(uint32_t*)(smc + SM_HBH + tid * 144 + 64 + j2 * 4);
        uint32_t vl = *(uint32_t*)(smc + SM_HBL + tid * 144 + 64 + j2 * 4);
        __nv_bfloat162 bh = *(__nv_bfloat162*)&vh, bl = *(__nv_bfloat162*)&vl;
        h1f[2 * j2]     = __bfloat162float(bh.x) + __bfloat162float(bl.x);
        h1f[2 * j2 + 1] = __bfloat162float(bh.y) + __bfloat162float(bl.y);
    }
    if (ng < N_NODES) {
        float y = __ldg(bfc2);
        #pragma unroll
        for (int m = 0; m < 16; m++) {
            float a = sbfc1[m];
            #pragma unroll
            for (int j = 0; j < 32; j++) a += h1f[j] * sWfc1[j * 16 + m];
            y += fmaxf(a, 0.0f) * sWfc2[m];
        }
        out[ng] = y;
    }
}

extern "C" void kernel_launch(void* const* d_in, const int* in_sizes, int n_in,
                              void* d_out, int out_size) {
    const float* x    = (const float*)d_in[0];
    // d_in[1] edge_index, d_in[2..9] GCN weights: dead code in the reference model
    const float* Wtp  = (const float*)d_in[10];
    const float* btp  = (const float*)d_in[11];
    const float* Wih0 = (const float*)d_in[12];
    const float* Whh0 = (const float*)d_in[13];
    const float* bih0 = (const float*)d_in[14];
    const float* bhh0 = (const float*)d_in[15];
    const float* Wih1 = (const float*)d_in[16];
    const float* Whh1 = (const float*)d_in[17];
    const float* bih1 = (const float*)d_in[18];
    const float* bhh1 = (const float*)d_in[19];
    const float* Wfc1 = (const float*)d_in[20];
    const float* bfc1 = (const float*)d_in[21];
    const float* Wfc2 = (const float*)d_in[22];
    const float* bfc2 = (const float*)d_in[23];
    float* out = (float*)d_out;

    cudaFuncSetAttribute(lstm_hmma_kernel,
                         cudaFuncAttributeMaxDynamicSharedMemorySize, SMEM_BYTES);

    int grid = (N_NODES + THREADS - 1) / THREADS;   // 782
    lstm_hmma_kernel<<<grid, THREADS, SMEM_BYTES>>>(
        x, Wtp, btp, Wih0, Whh0, bih0, bhh0,
        Wih1, Whh1, bih1, bhh1, Wfc1, bfc1, Wfc2, bfc2, out);
}